// round 3
// baseline (speedup 1.0000x reference)
#include <cuda_runtime.h>
#include <cuda_bf16.h>
#include <cstdint>

// adj is (N+4)x(N+4), N=8192:
//   adj[i][i] = 1.0 (i<N); adj[i][j] = 0.25 (i,j>=N); else 0.
//
// Strategy: (1) flat, 128B-aligned, branch-free zero fill of the whole buffer
// (pure streaming-store roofline shape); (2) tiny patch kernel writing the
// 8192 diagonal ones + 16-element 0.25 block (~0.25MB extra traffic).

__global__ __launch_bounds__(256) void zero_fill_kernel(float4* __restrict__ out,
                                                        size_t nq) {
    const size_t stride = (size_t)gridDim.x * blockDim.x;
    size_t q = (size_t)blockIdx.x * blockDim.x + threadIdx.x;
    const float4 z = make_float4(0.f, 0.f, 0.f, 0.f);
    #pragma unroll 4
    for (; q < nq; q += stride) {
        __stcs(out + q, z);
    }
}

__global__ void patch_kernel(float* __restrict__ out, int M, int N) {
    const int i = blockIdx.x * blockDim.x + threadIdx.x;
    if (i < N) {
        // diagonal
        out[(size_t)i * (size_t)(M + 1)] = 1.0f;
    } else if (i < N + 16) {
        const int k = i - N;
        const int r = N + (k >> 2);
        const int c = N + (k & 3);
        out[(size_t)r * (size_t)M + (size_t)c] = 0.25f;
    }
}

extern "C" void kernel_launch(void* const* d_in, const int* in_sizes, int n_in,
                              void* d_out, int out_size) {
    (void)d_in; (void)in_sizes; (void)n_in;

    // out_size = M*M. Recover M (expected 8196).
    int M = (int)(sqrtf((float)(double)out_size));
    while ((long long)M * M > (long long)out_size) --M;
    while ((long long)(M + 1) * (M + 1) <= (long long)out_size) ++M;
    const int N = M - 4;

    // Flat zero fill: out_size divisible by 16 for M divisible by 4.
    const size_t nq = (size_t)out_size >> 2;   // number of float4s
    const int threads = 256;
    // Full-chip grid with several waves; grid-stride keeps it shape-robust.
    int blocks = 148 * 16;
    zero_fill_kernel<<<blocks, threads>>>((float4*)d_out, nq);

    // Patch diagonal + bottom-right block (runs after fill, same stream).
    const int p_threads = 256;
    const int p_blocks = (N + 16 + p_threads - 1) / p_threads;
    patch_kernel<<<p_blocks, p_threads>>>((float*)d_out, M, N);
}

// round 4
// speedup vs baseline: 1.1007x; 1.1007x over previous
#include <cuda_runtime.h>
#include <cuda_bf16.h>
#include <cstdint>

// adj is (N+4)x(N+4), N=8192:
//   adj[i][i] = 1.0 (i<N); adj[i][j] = 0.25 (i,j>=N); else 0.
//
// Single fused write-only fill at the HBM write roofline.
// Flat layout: block b owns float4 chunk [b*2048, (b+1)*2048); thread t writes
// q = b*2048 + t + 256*k for k=0..7 (8 independent STG.128.CS, no tail iter).
//
// Value logic hoisted per thread:
//  - A thread's 8 float4s span < M+1 elements, so at most ONE diagonal element
//    falls in its range -> one u32 division per thread, then 1 compare/store.
//  - The 0.25 block is 4 groups of 4 consecutive elements, each 4-aligned
//    (N, M divisible by 4) -> exactly one float4 each -> 4 equality checks.

__global__ __launch_bounds__(256) void adj_fill_kernel(float4* __restrict__ out,
                                                       unsigned M, unsigned N,
                                                       unsigned nq) {
    const unsigned q0 = blockIdx.x * 2048u + threadIdx.x;   // first float4 of thread
    const unsigned e0 = q0 << 2;                            // first element index
    const unsigned Mp1 = M + 1u;

    // Unique candidate diagonal element in this thread's span [e0, e0+7172).
    unsigned i0 = e0 / Mp1;
    unsigned dd = i0 * Mp1;
    if (dd < e0) { dd += Mp1; ++i0; }
    const bool has_diag = (i0 < N);          // else dd points past diagonal region
    const unsigned dq   = dd >> 2;           // float4 index holding the diagonal
    const unsigned dl   = dd & 3u;           // lane within it

    // 0.25 block: group g lives at float4 index bq0 + g*(M/4), g = 0..3.
    const unsigned Mq  = M >> 2;
    const unsigned bq0 = (N * M + N) >> 2;

    const float4 z = make_float4(0.f, 0.f, 0.f, 0.f);
    const float4 blk = make_float4(0.25f, 0.25f, 0.25f, 0.25f);

    if (blockIdx.x != gridDim.x - 1) {
        #pragma unroll
        for (int k = 0; k < 8; ++k) {
            const unsigned q = q0 + (unsigned)k * 256u;
            float4 v = z;
            if (has_diag && q == dq) {
                float* f = reinterpret_cast<float*>(&v);
                f[dl] = 1.0f;
            }
            const unsigned r = q - bq0;
            if (r == 0u || r == Mq || r == 2u * Mq || r == 3u * Mq) v = blk;
            __stcs(out + q, v);
        }
    } else {
        #pragma unroll
        for (int k = 0; k < 8; ++k) {
            const unsigned q = q0 + (unsigned)k * 256u;
            if (q >= nq) break;
            float4 v = z;
            if (has_diag && q == dq) {
                float* f = reinterpret_cast<float*>(&v);
                f[dl] = 1.0f;
            }
            const unsigned r = q - bq0;
            if (r == 0u || r == Mq || r == 2u * Mq || r == 3u * Mq) v = blk;
            __stcs(out + q, v);
        }
    }
}

extern "C" void kernel_launch(void* const* d_in, const int* in_sizes, int n_in,
                              void* d_out, int out_size) {
    (void)d_in; (void)in_sizes; (void)n_in;

    // out_size = M*M. Recover M (expected 8196).
    int M = (int)(sqrtf((float)(double)out_size));
    while ((long long)M * M > (long long)out_size) --M;
    while ((long long)(M + 1) * (M + 1) <= (long long)out_size) ++M;
    const int N = M - 4;

    const unsigned nq = (unsigned)((long long)out_size >> 2);  // float4 count
    const unsigned blocks = (nq + 2047u) / 2048u;              // 2048 float4s/block
    adj_fill_kernel<<<blocks, 256>>>((float4*)d_out, (unsigned)M, (unsigned)N, nq);
}

// round 5
// speedup vs baseline: 1.1417x; 1.0372x over previous
#include <cuda_runtime.h>
#include <cuda_bf16.h>
#include <cstdint>

// adj is (N+4)x(N+4), N=8192:
//   adj[i][i] = 1.0 (i<N); adj[i][j] = 0.25 (i,j>=N); else 0.
//
// Hot loop = pure unconditional 256-bit zero stores (STG.256.CS, Blackwell).
// Rare nonzeros are patched by the OWNING thread after its zero stores
// (same thread + same address => program-order visibility).
//
// Layout: block b owns float8 chunk [b*1024, (b+1)*1024); thread t stores
// q8 = b*1024 + t + 256*k, k=0..3. Thread element span (3*2048+8)=6152 < M+1,
// so each thread contains at most ONE diagonal element. Each 4-wide 0.25
// group starts at element offset mod 8 in {0,4}, so it lies in ONE float8
// and is 16B-aligned (float4 patch store).

__global__ __launch_bounds__(256) void adj_fill_kernel(float* __restrict__ out,
                                                       unsigned M, unsigned N,
                                                       unsigned nq8) {
    const unsigned q80 = blockIdx.x * 1024u + threadIdx.x;
    const bool full = (blockIdx.x != gridDim.x - 1);

    // ---- hot loop: 4 unconditional 256-bit zero stores ----
    #pragma unroll
    for (int k = 0; k < 4; ++k) {
        const unsigned q8 = q80 + (unsigned)k * 256u;
        if (full || q8 < nq8) {
            float* p = out + (size_t)q8 * 8u;
            asm volatile(
                "st.global.cs.v8.f32 [%0], {%1,%2,%3,%4,%5,%6,%7,%8};"
                :: "l"(p),
                   "f"(0.f), "f"(0.f), "f"(0.f), "f"(0.f),
                   "f"(0.f), "f"(0.f), "f"(0.f), "f"(0.f)
                : "memory");
        }
    }

    // ---- rare epilogue patches (same-thread overwrite of own zero store) ----
    const unsigned e0  = q80 << 3;          // first element this thread wrote
    const unsigned Mp1 = M + 1u;

    // diagonal: unique candidate element dd in this thread's span
    unsigned i0 = e0 / Mp1;
    unsigned dd = i0 * Mp1;
    if (dd < e0) { dd += Mp1; ++i0; }
    if (i0 < N) {
        const unsigned d8  = dd >> 3;
        const unsigned rel = d8 - q80;      // underflow -> huge -> fails checks
        if (rel < 1024u && (rel & 255u) == 0u) {
            out[dd] = 1.0f;
        }
    }

    // bottom-right 4x4 block of 0.25: 4 groups of 4 consecutive elements
    const unsigned base = N * M + N;
    #pragma unroll
    for (unsigned g = 0; g < 4; ++g) {
        const unsigned eg  = base + g * M;
        const unsigned f8  = eg >> 3;
        const unsigned rel = f8 - q80;
        if (rel < 1024u && (rel & 255u) == 0u) {
            *reinterpret_cast<float4*>(out + eg) =
                make_float4(0.25f, 0.25f, 0.25f, 0.25f);
        }
    }
}

extern "C" void kernel_launch(void* const* d_in, const int* in_sizes, int n_in,
                              void* d_out, int out_size) {
    (void)d_in; (void)in_sizes; (void)n_in;

    // out_size = M*M. Recover M (expected 8196).
    int M = (int)(sqrtf((float)(double)out_size));
    while ((long long)M * M > (long long)out_size) --M;
    while ((long long)(M + 1) * (M + 1) <= (long long)out_size) ++M;
    const int N = M - 4;

    const unsigned nq8 = (unsigned)((long long)out_size >> 3);   // float8 count
    const unsigned blocks = (nq8 + 1023u) / 1024u;               // 1024 float8/block
    adj_fill_kernel<<<blocks, 256>>>((float*)d_out, (unsigned)M, (unsigned)N, nq8);
}